// round 3
// baseline (speedup 1.0000x reference)
#include <cuda_runtime.h>
#include <stdint.h>

// Problem constants (fixed by the reference)
#define NXD 512
#define NYD 512
#define CH  128
#define BATCH 4
#define CELLS (NYD * NXD)              // 262144 cells per batch
#define TOTAL_CELLS (BATCH * CELLS)    // 1,048,576

// Scratch: per-cell pillar index (-1 = empty). 4 MiB static device array.
__device__ int g_idx[TOTAL_CELLS];
// Zero feature row for empty cells (zero-initialized, read-only -> stays hot in L2).
__device__ float4 g_zero_row[CH / 4];

// ---------------------------------------------------------------------------
// Pass 1: fill index canvas with -1 (vectorized int4 stores, 4 MiB)
// ---------------------------------------------------------------------------
__global__ void init_idx_kernel() {
    int t = blockIdx.x * blockDim.x + threadIdx.x;   // TOTAL_CELLS/4 threads
    if (t < TOTAL_CELLS / 4)
        ((int4*)g_idx)[t] = make_int4(-1, -1, -1, -1);
}

// ---------------------------------------------------------------------------
// Pass 2: scatter pillar index into canvas. coords row = [b, z, y, x], NZ=1.
// ---------------------------------------------------------------------------
__global__ void build_idx_kernel(const int* __restrict__ coords, int P) {
    int p = blockIdx.x * blockDim.x + threadIdx.x;
    if (p >= P) return;
    int4 c = ((const int4*)coords)[p];               // b, z, y, x
    // flat = ((b*NZ + z)*NY + y)*NX + x ; NZ == 1
    int cell = (c.x + c.y) * CELLS + c.z * NXD + c.w;
    g_idx[cell] = p;
}

// ---------------------------------------------------------------------------
// Pass 3: gather. Each thread owns 4 consecutive x-cells of one (b, y) row.
// For each channel c the warp stores 32 float4 = 512 contiguous bytes.
// Feature rows are read as float4 along c (512 B sequential per pillar row),
// transposed in registers.
// ---------------------------------------------------------------------------
__global__ __launch_bounds__(256) void gather_kernel(
    const float* __restrict__ feat, float* __restrict__ out)
{
    int t  = blockIdx.x * blockDim.x + threadIdx.x;  // TOTAL_CELLS/4 threads
    if (t >= TOTAL_CELLS / 4) return;
    int xg = (t & 127) << 2;                         // x base (0,4,...,508)
    int y  = (t >> 7) & 511;
    int b  = t >> 16;                                // 65536 threads per batch

    int cell = (b << 18) + (y << 9) + xg;
    int p0 = g_idx[cell + 0];
    int p1 = g_idx[cell + 1];
    int p2 = g_idx[cell + 2];
    int p3 = g_idx[cell + 3];

    const float4* r0 = (p0 >= 0) ? (const float4*)(feat + (size_t)p0 * CH) : g_zero_row;
    const float4* r1 = (p1 >= 0) ? (const float4*)(feat + (size_t)p1 * CH) : g_zero_row;
    const float4* r2 = (p2 >= 0) ? (const float4*)(feat + (size_t)p2 * CH) : g_zero_row;
    const float4* r3 = (p3 >= 0) ? (const float4*)(feat + (size_t)p3 * CH) : g_zero_row;

    float4* obase = (float4*)(out + (size_t)b * CH * CELLS + (y << 9) + xg);
    // Channel stride in float4 units: CELLS/4 = 65536
    #pragma unroll 4
    for (int cc = 0; cc < CH / 4; ++cc) {
        float4 a = __ldg(r0 + cc);
        float4 e = __ldg(r1 + cc);
        float4 f = __ldg(r2 + cc);
        float4 g = __ldg(r3 + cc);
        obase[(size_t)(4 * cc + 0) * 65536] = make_float4(a.x, e.x, f.x, g.x);
        obase[(size_t)(4 * cc + 1) * 65536] = make_float4(a.y, e.y, f.y, g.y);
        obase[(size_t)(4 * cc + 2) * 65536] = make_float4(a.z, e.z, f.z, g.z);
        obase[(size_t)(4 * cc + 3) * 65536] = make_float4(a.w, e.w, f.w, g.w);
    }
}

// ---------------------------------------------------------------------------
// Launch: identify inputs by size (batch_size scalar / features / coords),
// then run the three passes on the capture stream.
// ---------------------------------------------------------------------------
extern "C" void kernel_launch(void* const* d_in, const int* in_sizes, int n_in,
                              void* d_out, int out_size)
{
    // features is the largest input (P*128 floats); coords has P*4 ints.
    int fi = 0;
    long long best = -1;
    for (int i = 0; i < n_in; ++i) {
        if ((long long)in_sizes[i] > best) { best = in_sizes[i]; fi = i; }
    }
    const float* feat = (const float*)d_in[fi];
    int P = in_sizes[fi] / CH;

    const int* coords = nullptr;
    for (int i = 0; i < n_in; ++i) {
        if (i != fi && in_sizes[i] == P * 4) { coords = (const int*)d_in[i]; break; }
    }
    if (!coords) { // fallback: second-largest input
        int ci = -1; long long b2 = -1;
        for (int i = 0; i < n_in; ++i)
            if (i != fi && (long long)in_sizes[i] > b2) { b2 = in_sizes[i]; ci = i; }
        coords = (const int*)d_in[ci];
    }

    float* out = (float*)d_out;

    // Pass 1: reset index canvas (262144 int4 stores)
    init_idx_kernel<<<(TOTAL_CELLS / 4 + 255) / 256, 256>>>();
    // Pass 2: scatter pillar indices
    build_idx_kernel<<<(P + 255) / 256, 256>>>(coords, P);
    // Pass 3: gather + transpose into the BEV canvas
    gather_kernel<<<(TOTAL_CELLS / 4 + 255) / 256, 256>>>(feat, out);
}

// round 5
// speedup vs baseline: 1.1395x; 1.1395x over previous
#include <cuda_runtime.h>
#include <stdint.h>

// Problem constants (fixed by the reference)
#define NXD 512
#define NYD 512
#define CH  128
#define BATCH 4
#define CELLS (NYD * NXD)              // 262144 cells per batch
#define TOTAL_CELLS (BATCH * CELLS)    // 1,048,576

// Scratch: per-cell pillar index. Self-verifying: an entry p is live only if
// coords[p] maps back to this cell, so NO reset pass is needed (zero-init at
// module load; stale entries from prior replays are re-validated or rejected).
__device__ int g_idx[TOTAL_CELLS];
// Zero feature row for empty cells (zero-initialized, read-only -> hot in L2/L1).
__device__ float4 g_zero_row[CH / 4];

// ---------------------------------------------------------------------------
// Pass 1: scatter pillar index into canvas. coords row = [b, z, y, x], NZ=1.
// ---------------------------------------------------------------------------
__global__ void build_idx_kernel(const int* __restrict__ coords, int P) {
    int p = blockIdx.x * blockDim.x + threadIdx.x;
    if (p >= P) return;
    int4 c = ((const int4*)coords)[p];               // b, z, y, x
    int cell = (c.x + c.y) * CELLS + c.z * NXD + c.w;
    g_idx[cell] = p;
}

// ---------------------------------------------------------------------------
// Pass 2: gather. Each thread owns 4 consecutive x-cells of one (b, y) row.
// For each channel c the warp stores 32 float4 = 512 contiguous bytes (512B-
// aligned). Feature rows are read as float4 along c and transposed in regs.
// ---------------------------------------------------------------------------
__device__ __forceinline__ const float4* resolve_row(
    int p, int cell, int P, const float* feat, const int4* coords4)
{
    if ((unsigned)p < (unsigned)P) {
        int4 c = __ldg(coords4 + p);
        int pc = (c.x + c.y) * CELLS + c.z * NXD + c.w;
        if (pc == cell)
            return (const float4*)(feat + (size_t)p * CH);
    }
    return g_zero_row;
}

__global__ __launch_bounds__(256) void gather_kernel(
    const float* __restrict__ feat, const int4* __restrict__ coords4,
    float* __restrict__ out, int P)
{
    int t  = blockIdx.x * blockDim.x + threadIdx.x;  // TOTAL_CELLS/4 threads
    if (t >= TOTAL_CELLS / 4) return;
    int xg = (t & 127) << 2;                         // x base (0,4,...,508)
    int y  = (t >> 7) & 511;
    int b  = t >> 16;                                // 65536 threads per batch

    int cell = (b << 18) + (y << 9) + xg;
    int4 pq = __ldg((const int4*)g_idx + (cell >> 2));   // 4 cell indices at once

    const float4* r0 = resolve_row(pq.x, cell + 0, P, feat, coords4);
    const float4* r1 = resolve_row(pq.y, cell + 1, P, feat, coords4);
    const float4* r2 = resolve_row(pq.z, cell + 2, P, feat, coords4);
    const float4* r3 = resolve_row(pq.w, cell + 3, P, feat, coords4);

    float4* obase = (float4*)(out + (size_t)b * CH * CELLS + (y << 9) + xg);
    // Channel stride in float4 units: CELLS/4 = 65536
    #pragma unroll 8
    for (int cc = 0; cc < CH / 4; ++cc) {
        float4 a = __ldg(r0 + cc);
        float4 e = __ldg(r1 + cc);
        float4 f = __ldg(r2 + cc);
        float4 g = __ldg(r3 + cc);
        obase[(size_t)(4 * cc + 0) * 65536] = make_float4(a.x, e.x, f.x, g.x);
        obase[(size_t)(4 * cc + 1) * 65536] = make_float4(a.y, e.y, f.y, g.y);
        obase[(size_t)(4 * cc + 2) * 65536] = make_float4(a.z, e.z, f.z, g.z);
        obase[(size_t)(4 * cc + 3) * 65536] = make_float4(a.w, e.w, f.w, g.w);
    }
}

// ---------------------------------------------------------------------------
// Launch: identify inputs by size (batch_size scalar / features / coords).
// ---------------------------------------------------------------------------
extern "C" void kernel_launch(void* const* d_in, const int* in_sizes, int n_in,
                              void* d_out, int out_size)
{
    // features is the largest input (P*128 floats); coords has P*4 ints.
    int fi = 0;
    long long best = -1;
    for (int i = 0; i < n_in; ++i) {
        if ((long long)in_sizes[i] > best) { best = in_sizes[i]; fi = i; }
    }
    const float* feat = (const float*)d_in[fi];
    int P = in_sizes[fi] / CH;

    const int* coords = nullptr;
    for (int i = 0; i < n_in; ++i) {
        if (i != fi && in_sizes[i] == P * 4) { coords = (const int*)d_in[i]; break; }
    }
    if (!coords) { // fallback: second-largest input
        int ci = -1; long long b2 = -1;
        for (int i = 0; i < n_in; ++i)
            if (i != fi && (long long)in_sizes[i] > b2) { b2 = in_sizes[i]; ci = i; }
        coords = (const int*)d_in[ci];
    }

    float* out = (float*)d_out;

    // Pass 1: scatter pillar indices (self-verifying canvas, no reset needed)
    build_idx_kernel<<<(P + 255) / 256, 256>>>(coords, P);
    // Pass 2: gather + transpose into the BEV canvas
    gather_kernel<<<(TOTAL_CELLS / 4 + 255) / 256, 256>>>(
        feat, (const int4*)coords, out, P);
}

// round 6
// speedup vs baseline: 1.1637x; 1.0212x over previous
#include <cuda_runtime.h>
#include <stdint.h>

// Problem constants (fixed by the reference)
#define NXD 512
#define NYD 512
#define CH  128
#define BATCH 4
#define CELLS (NYD * NXD)              // 262144 cells per batch
#define TOTAL_CELLS (BATCH * CELLS)    // 1,048,576

// Scratch: per-cell pillar index. Self-verifying: an entry p is live only if
// coords[p] maps back to this cell, so NO reset pass is needed (zero-init at
// module load; stale entries from prior replays are re-validated or rejected).
__device__ int g_idx[TOTAL_CELLS];
// Zero feature row for empty cells (zero-initialized, read-only -> hot in L1/L2,
// broadcast across lanes).
__device__ float4 g_zero_row[CH / 4];

// ---------------------------------------------------------------------------
// Pass 1: scatter pillar index into canvas. coords row = [b, z, y, x], NZ=1.
// ---------------------------------------------------------------------------
__global__ void build_idx_kernel(const int* __restrict__ coords, int P) {
    int p = blockIdx.x * blockDim.x + threadIdx.x;
    if (p >= P) return;
    int4 c = ((const int4*)coords)[p];               // b, z, y, x
    int cell = (c.x + c.y) * CELLS + c.z * NXD + c.w;
    g_idx[cell] = p;
}

// ---------------------------------------------------------------------------
// Pass 2: gather. ONE cell per thread (1M threads). Warp = 32 consecutive x
// cells, so each scalar channel store is 128 contiguous bytes per warp (zero
// sector amplification). Feature row read as float4 along the channel dim.
// Low register footprint -> high occupancy -> latency hiding.
// ---------------------------------------------------------------------------
__global__ __launch_bounds__(256) void gather_kernel(
    const float* __restrict__ feat, const int4* __restrict__ coords4,
    float* __restrict__ out, int P)
{
    int t = blockIdx.x * blockDim.x + threadIdx.x;   // TOTAL_CELLS threads
    if (t >= TOTAL_CELLS) return;

    int cell = t;                                    // b*CELLS*? : layout below
    int p = __ldg(g_idx + cell);                     // coalesced 128B/warp

    const float4* r = g_zero_row;
    if ((unsigned)p < (unsigned)P) {
        int4 c = __ldg(coords4 + p);
        int pc = (c.x + c.y) * CELLS + c.z * NXD + c.w;
        if (pc == cell)
            r = (const float4*)(feat + (size_t)p * CH);
    }

    // out[b][c][y][x]: b = t>>18, (y,x) offset = t & (CELLS-1)
    float* obase = out + ((size_t)(t >> 18) * CH) * CELLS + (t & (CELLS - 1));

    #pragma unroll 8
    for (int cc = 0; cc < CH / 4; ++cc) {
        float4 v = __ldg(r + cc);
        obase[(size_t)(4 * cc + 0) * CELLS] = v.x;
        obase[(size_t)(4 * cc + 1) * CELLS] = v.y;
        obase[(size_t)(4 * cc + 2) * CELLS] = v.z;
        obase[(size_t)(4 * cc + 3) * CELLS] = v.w;
    }
}

// ---------------------------------------------------------------------------
// Launch: identify inputs by size (batch_size scalar / features / coords).
// ---------------------------------------------------------------------------
extern "C" void kernel_launch(void* const* d_in, const int* in_sizes, int n_in,
                              void* d_out, int out_size)
{
    // features is the largest input (P*128 floats); coords has P*4 ints.
    int fi = 0;
    long long best = -1;
    for (int i = 0; i < n_in; ++i) {
        if ((long long)in_sizes[i] > best) { best = in_sizes[i]; fi = i; }
    }
    const float* feat = (const float*)d_in[fi];
    int P = in_sizes[fi] / CH;

    const int* coords = nullptr;
    for (int i = 0; i < n_in; ++i) {
        if (i != fi && in_sizes[i] == P * 4) { coords = (const int*)d_in[i]; break; }
    }
    if (!coords) { // fallback: second-largest input
        int ci = -1; long long b2 = -1;
        for (int i = 0; i < n_in; ++i)
            if (i != fi && (long long)in_sizes[i] > b2) { b2 = in_sizes[i]; ci = i; }
        coords = (const int*)d_in[ci];
    }

    float* out = (float*)d_out;

    // Pass 1: scatter pillar indices (self-verifying canvas, no reset needed)
    build_idx_kernel<<<(P + 255) / 256, 256>>>(coords, P);
    // Pass 2: gather + transpose into the BEV canvas (1 thread per cell)
    gather_kernel<<<TOTAL_CELLS / 256, 256>>>(
        feat, (const int4*)coords, out, P);
}

// round 7
// speedup vs baseline: 1.2312x; 1.0580x over previous
#include <cuda_runtime.h>
#include <stdint.h>

// Problem constants (fixed by the reference)
#define NXD 512
#define NYD 512
#define CH  128
#define HALF_CH 64
#define BATCH 4
#define CELLS (NYD * NXD)              // 262144 cells per batch
#define TOTAL_CELLS (BATCH * CELLS)    // 1,048,576  (= 1<<20)

// Scratch: per-cell pillar index, reset to -1 each call via a 0xFF memset node.
__device__ int g_idx[TOTAL_CELLS];
// Zero feature row for empty cells (zero-initialized, read-only -> hot in L2).
__device__ float4 g_zero_row[CH / 4];

// ---------------------------------------------------------------------------
// Pass 1: scatter pillar index into canvas. coords row = [b, z, y, x], NZ=1.
// ---------------------------------------------------------------------------
__global__ void build_idx_kernel(const int* __restrict__ coords, int P) {
    int p = blockIdx.x * blockDim.x + threadIdx.x;
    if (p >= P) return;
    int4 c = ((const int4*)coords)[p];               // b, z, y, x
    int cell = (c.x + c.y) * CELLS + c.z * NXD + c.w;
    g_idx[cell] = p;
}

// ---------------------------------------------------------------------------
// Pass 2: gather. TWO threads per cell, each owning 64 channels; the channel
// half is selected by the grid half so that consecutive threads still map to
// consecutive x cells (warp store = 128 contiguous bytes, zero amplification).
// Dependent chain is only idx -> feat (no coords verification; canvas is
// freshly memset to -1 every call).
// ---------------------------------------------------------------------------
__global__ __launch_bounds__(256) void gather_kernel(
    const float* __restrict__ feat, float* __restrict__ out, int P)
{
    int t = blockIdx.x * blockDim.x + threadIdx.x;   // 2*TOTAL_CELLS threads
    int half = t >> 20;                              // 0: ch 0-63, 1: ch 64-127
    int cell = t & (TOTAL_CELLS - 1);

    int p = __ldg(g_idx + cell);                     // coalesced 128B/warp

    const float4* r = (p >= 0)
        ? (const float4*)(feat + (size_t)p * CH + half * HALF_CH)
        : (g_zero_row + half * (HALF_CH / 4));

    int b = cell >> 18;                              // batch
    float* obase = out + (size_t)(b * CH + half * HALF_CH) * CELLS
                       + (cell & (CELLS - 1));

    #pragma unroll 8
    for (int cc = 0; cc < HALF_CH / 4; ++cc) {       // 16 float4 loads
        float4 v = __ldg(r + cc);
        obase[(size_t)(4 * cc + 0) * CELLS] = v.x;
        obase[(size_t)(4 * cc + 1) * CELLS] = v.y;
        obase[(size_t)(4 * cc + 2) * CELLS] = v.z;
        obase[(size_t)(4 * cc + 3) * CELLS] = v.w;
    }
}

// ---------------------------------------------------------------------------
// Launch: identify inputs by size (batch_size scalar / features / coords).
// ---------------------------------------------------------------------------
extern "C" void kernel_launch(void* const* d_in, const int* in_sizes, int n_in,
                              void* d_out, int out_size)
{
    // features is the largest input (P*128 floats); coords has P*4 ints.
    int fi = 0;
    long long best = -1;
    for (int i = 0; i < n_in; ++i) {
        if ((long long)in_sizes[i] > best) { best = in_sizes[i]; fi = i; }
    }
    const float* feat = (const float*)d_in[fi];
    int P = in_sizes[fi] / CH;

    const int* coords = nullptr;
    for (int i = 0; i < n_in; ++i) {
        if (i != fi && in_sizes[i] == P * 4) { coords = (const int*)d_in[i]; break; }
    }
    if (!coords) { // fallback: second-largest input
        int ci = -1; long long b2 = -1;
        for (int i = 0; i < n_in; ++i)
            if (i != fi && (long long)in_sizes[i] > b2) { b2 = in_sizes[i]; ci = i; }
        coords = (const int*)d_in[ci];
    }

    float* out = (float*)d_out;

    // Pass 0: reset index canvas to -1 (0xFF bytes). Memset node: capturable,
    // no allocation, ~1us for 4 MiB.
    void* idx_ptr = nullptr;
    cudaGetSymbolAddress(&idx_ptr, g_idx);
    cudaMemsetAsync(idx_ptr, 0xFF, TOTAL_CELLS * sizeof(int), 0);

    // Pass 1: scatter pillar indices
    build_idx_kernel<<<(P + 255) / 256, 256>>>(coords, P);

    // Pass 2: gather + transpose into the BEV canvas (2 threads per cell)
    gather_kernel<<<(2 * TOTAL_CELLS) / 256, 256>>>(feat, out, P);
}

// round 8
// speedup vs baseline: 1.2376x; 1.0052x over previous
#include <cuda_runtime.h>
#include <stdint.h>

// Problem constants (fixed by the reference)
#define NXD 512
#define NYD 512
#define CH  128
#define QCH 32                          // channels per thread (quarter row)
#define BATCH 4
#define CELLS (NYD * NXD)               // 262144 cells per batch
#define TOTAL_CELLS (BATCH * CELLS)     // 1,048,576  (= 1<<20)

// Scratch: per-cell pillar index, reset to -1 each call via a 0xFF memset node.
__device__ int g_idx[TOTAL_CELLS];
// Zero feature row for empty cells (zero-initialized, read-only -> hot in L2).
__device__ float4 g_zero_row[CH / 4];

// ---------------------------------------------------------------------------
// Pass 1: scatter pillar index into canvas. coords row = [b, z, y, x], NZ=1.
// ---------------------------------------------------------------------------
__global__ void build_idx_kernel(const int* __restrict__ coords, int P) {
    int p = blockIdx.x * blockDim.x + threadIdx.x;
    if (p >= P) return;
    int4 c = ((const int4*)coords)[p];               // b, z, y, x
    int cell = (c.x + c.y) * CELLS + c.z * NXD + c.w;
    g_idx[cell] = p;
}

// ---------------------------------------------------------------------------
// Pass 2: gather. FOUR threads per cell, each owning 32 channels (selected by
// grid quarter so consecutive threads map to consecutive x cells -> every
// warp store is 128 contiguous bytes). All 8 float4 feature loads are issued
// front-batched into named registers (MLP_p1 = 8 in SASS) before any store.
// ---------------------------------------------------------------------------
__global__ __launch_bounds__(256, 5) void gather_kernel(
    const float* __restrict__ feat, float* __restrict__ out)
{
    int t = blockIdx.x * blockDim.x + threadIdx.x;   // 4*TOTAL_CELLS threads
    int q    = t >> 20;                              // quarter: ch [32q, 32q+32)
    int cell = t & (TOTAL_CELLS - 1);

    int p = __ldg(g_idx + cell);                     // coalesced 128B/warp

    const float4* r = (p >= 0)
        ? (const float4*)(feat + (size_t)p * CH + q * QCH)
        : (g_zero_row + q * (QCH / 4));

    // Front-batch all 8 loads (512B per lane quarter-row)
    float4 v0 = __ldg(r + 0);
    float4 v1 = __ldg(r + 1);
    float4 v2 = __ldg(r + 2);
    float4 v3 = __ldg(r + 3);
    float4 v4 = __ldg(r + 4);
    float4 v5 = __ldg(r + 5);
    float4 v6 = __ldg(r + 6);
    float4 v7 = __ldg(r + 7);

    int b = cell >> 18;                              // batch
    float* o = out + (size_t)(b * CH + q * QCH) * CELLS + (cell & (CELLS - 1));

    o[(size_t) 0 * CELLS] = v0.x;  o[(size_t) 1 * CELLS] = v0.y;
    o[(size_t) 2 * CELLS] = v0.z;  o[(size_t) 3 * CELLS] = v0.w;
    o[(size_t) 4 * CELLS] = v1.x;  o[(size_t) 5 * CELLS] = v1.y;
    o[(size_t) 6 * CELLS] = v1.z;  o[(size_t) 7 * CELLS] = v1.w;
    o[(size_t) 8 * CELLS] = v2.x;  o[(size_t) 9 * CELLS] = v2.y;
    o[(size_t)10 * CELLS] = v2.z;  o[(size_t)11 * CELLS] = v2.w;
    o[(size_t)12 * CELLS] = v3.x;  o[(size_t)13 * CELLS] = v3.y;
    o[(size_t)14 * CELLS] = v3.z;  o[(size_t)15 * CELLS] = v3.w;
    o[(size_t)16 * CELLS] = v4.x;  o[(size_t)17 * CELLS] = v4.y;
    o[(size_t)18 * CELLS] = v4.z;  o[(size_t)19 * CELLS] = v4.w;
    o[(size_t)20 * CELLS] = v5.x;  o[(size_t)21 * CELLS] = v5.y;
    o[(size_t)22 * CELLS] = v5.z;  o[(size_t)23 * CELLS] = v5.w;
    o[(size_t)24 * CELLS] = v6.x;  o[(size_t)25 * CELLS] = v6.y;
    o[(size_t)26 * CELLS] = v6.z;  o[(size_t)27 * CELLS] = v6.w;
    o[(size_t)28 * CELLS] = v7.x;  o[(size_t)29 * CELLS] = v7.y;
    o[(size_t)30 * CELLS] = v7.z;  o[(size_t)31 * CELLS] = v7.w;
}

// ---------------------------------------------------------------------------
// Launch: identify inputs by size (batch_size scalar / features / coords).
// ---------------------------------------------------------------------------
extern "C" void kernel_launch(void* const* d_in, const int* in_sizes, int n_in,
                              void* d_out, int out_size)
{
    // features is the largest input (P*128 floats); coords has P*4 ints.
    int fi = 0;
    long long best = -1;
    for (int i = 0; i < n_in; ++i) {
        if ((long long)in_sizes[i] > best) { best = in_sizes[i]; fi = i; }
    }
    const float* feat = (const float*)d_in[fi];
    int P = in_sizes[fi] / CH;

    const int* coords = nullptr;
    for (int i = 0; i < n_in; ++i) {
        if (i != fi && in_sizes[i] == P * 4) { coords = (const int*)d_in[i]; break; }
    }
    if (!coords) { // fallback: second-largest input
        int ci = -1; long long b2 = -1;
        for (int i = 0; i < n_in; ++i)
            if (i != fi && (long long)in_sizes[i] > b2) { b2 = in_sizes[i]; ci = i; }
        coords = (const int*)d_in[ci];
    }

    float* out = (float*)d_out;

    // Pass 0: reset index canvas to -1 (0xFF bytes). Memset node: capturable,
    // no allocation, ~1us for 4 MiB.
    void* idx_ptr = nullptr;
    cudaGetSymbolAddress(&idx_ptr, g_idx);
    cudaMemsetAsync(idx_ptr, 0xFF, TOTAL_CELLS * sizeof(int), 0);

    // Pass 1: scatter pillar indices
    build_idx_kernel<<<(P + 255) / 256, 256>>>(coords, P);

    // Pass 2: gather + transpose into the BEV canvas (4 threads per cell)
    gather_kernel<<<(4 * TOTAL_CELLS) / 256, 256>>>(feat, out);
}